// round 1
// baseline (speedup 1.0000x reference)
#include <cuda_runtime.h>
#include <cuda_bf16.h>
#include <math.h>

// Problem constants
#define B_     2
#define T_     2048
#define CMODEL 1024
#define NHEADS 16
#define DHEAD  64
#define NTOK   (B_ * T_)          // 4096
#define F3     (3 * CMODEL)       // 3072

// Scratch (static device arrays — no runtime allocation)
__device__ float g_qkv[NTOK * F3];        // [n][3072]  (q|k|v per token)
__device__ float g_attn[NTOK * CMODEL];   // [n][1024]  attention output, [b,t,h,d]

// ---------------------------------------------------------------------------
// SGEMM: C[M,N] = A[M,K] * B[N,K]^T   (both row-major, K contiguous)
// 128x128 block tile, BK=16, 256 threads, 8x8 per-thread microtile.
// ---------------------------------------------------------------------------
#define BM 128
#define BN 128
#define BK 16

__global__ __launch_bounds__(256) void sgemm_nt(
    const float* __restrict__ A, const float* __restrict__ Bm,
    float* __restrict__ C, int M, int N, int K)
{
    __shared__ float As[BK][BM + 4];
    __shared__ float Bs[BK][BN + 4];

    const int bx = blockIdx.x;   // N tile
    const int by = blockIdx.y;   // M tile
    const int tid = threadIdx.x;
    const int tx = tid & 15;
    const int ty = tid >> 4;

    float acc[8][8];
#pragma unroll
    for (int i = 0; i < 8; i++)
#pragma unroll
        for (int j = 0; j < 8; j++) acc[i][j] = 0.f;

    const float4* A4 = reinterpret_cast<const float4*>(A);
    const float4* B4 = reinterpret_cast<const float4*>(Bm);
    const int K4 = K >> 2;

    for (int k0 = 0; k0 < K; k0 += BK) {
        const int k04 = k0 >> 2;
        // Load A tile: 128 rows x 16 k = 512 float4, 2 per thread
#pragma unroll
        for (int i = 0; i < 2; i++) {
            int s = tid + i * 256;
            int row = s >> 2, kq = s & 3;
            float4 v = A4[(size_t)(by * BM + row) * K4 + k04 + kq];
            As[kq * 4 + 0][row] = v.x;
            As[kq * 4 + 1][row] = v.y;
            As[kq * 4 + 2][row] = v.z;
            As[kq * 4 + 3][row] = v.w;
        }
        // Load B tile (B is [N,K] row-major): 128 rows(f) x 16 k
#pragma unroll
        for (int i = 0; i < 2; i++) {
            int s = tid + i * 256;
            int row = s >> 2, kq = s & 3;
            float4 v = B4[(size_t)(bx * BN + row) * K4 + k04 + kq];
            Bs[kq * 4 + 0][row] = v.x;
            Bs[kq * 4 + 1][row] = v.y;
            Bs[kq * 4 + 2][row] = v.z;
            Bs[kq * 4 + 3][row] = v.w;
        }
        __syncthreads();

#pragma unroll
        for (int kk = 0; kk < BK; kk++) {
            float a[8], b[8];
#pragma unroll
            for (int i = 0; i < 8; i++) a[i] = As[kk][ty + i * 16];
#pragma unroll
            for (int j = 0; j < 8; j++) b[j] = Bs[kk][tx + j * 16];
#pragma unroll
            for (int i = 0; i < 8; i++)
#pragma unroll
                for (int j = 0; j < 8; j++) acc[i][j] += a[i] * b[j];
        }
        __syncthreads();
    }

#pragma unroll
    for (int i = 0; i < 8; i++) {
        int row = by * BM + ty + i * 16;
#pragma unroll
        for (int j = 0; j < 8; j++) {
            int col = bx * BN + tx + j * 16;
            C[(size_t)row * N + col] = acc[i][j];
        }
    }
}

// ---------------------------------------------------------------------------
// Flash attention (causal), fp32.
// Grid: (T/64, NHEADS, B). 256 threads = 64 rows x 4 lanes/row.
// Reads Q/K/V strided out of g_qkv, writes g_attn[n][h*64+d].
// Dynamic smem: Qs,Ks,Vs,Ps each 64 x 68 floats (stride 68 = 17 float4).
// ---------------------------------------------------------------------------
#define ROWSTR 68          // floats
#define ROWSTR4 17         // float4
#define TILE_F4 (64 * 16)  // 1024 float4 per 64x64 tile
#define SMEM_ATTN (4 * 64 * ROWSTR * 4)   // 69632 bytes

__global__ __launch_bounds__(256) void attn_causal_kernel()
{
    extern __shared__ float sm[];
    float* Qs = sm;
    float* Ks = sm + 64 * ROWSTR;
    float* Vs = sm + 2 * 64 * ROWSTR;
    float* Ps = sm + 3 * 64 * ROWSTR;

    const int ib = blockIdx.x;    // query row-tile
    const int h  = blockIdx.y;
    const int b  = blockIdx.z;
    const int tid = threadIdx.x;
    const int r = tid >> 2;       // row within tile 0..63
    const int q = tid & 3;        // lane within row-group

    const float4* qkv4 = reinterpret_cast<const float4*>(g_qkv);
    const int rowstride4 = F3 >> 2;      // 768
    const int hoff4 = h * (DHEAD >> 2);  // h*16

    // Load Q tile
    {
        const int rb = b * T_ + ib * 64;
        for (int i = tid; i < TILE_F4; i += 256) {
            int row = i >> 4, c4 = i & 15;
            reinterpret_cast<float4*>(Qs)[row * ROWSTR4 + c4] =
                qkv4[(size_t)(rb + row) * rowstride4 + hoff4 + c4];
        }
    }

    float m = -1e30f, l = 0.f;
    float4 o[4];
#pragma unroll
    for (int u = 0; u < 4; u++) o[u] = make_float4(0.f, 0.f, 0.f, 0.f);

    const int tglob = ib * 64 + r;

    for (int jb = 0; jb <= ib; jb++) {
        __syncthreads();   // protect Vs/Ks from previous iteration + Qs first iter
        {
            const int kb = b * T_ + jb * 64;
            for (int i = tid; i < TILE_F4; i += 256) {
                int row = i >> 4, c4 = i & 15;
                size_t base = (size_t)(kb + row) * rowstride4;
                reinterpret_cast<float4*>(Ks)[row * ROWSTR4 + c4] =
                    qkv4[base + 256 + hoff4 + c4];   // K at +1024 floats
                reinterpret_cast<float4*>(Vs)[row * ROWSTR4 + c4] =
                    qkv4[base + 512 + hoff4 + c4];   // V at +2048 floats
            }
        }
        __syncthreads();

        // S = Q K^T  (thread owns columns j = q + 4*jj)
        float s[16];
#pragma unroll
        for (int jj = 0; jj < 16; jj++) s[jj] = 0.f;
        const float4* Qr = reinterpret_cast<const float4*>(Qs) + r * ROWSTR4;
        const float4* K4s = reinterpret_cast<const float4*>(Ks);
#pragma unroll
        for (int d4 = 0; d4 < 16; d4++) {
            float4 qv = Qr[d4];
#pragma unroll
            for (int jj = 0; jj < 16; jj++) {
                float4 kv = K4s[(q + jj * 4) * ROWSTR4 + d4];
                s[jj] += qv.x * kv.x + qv.y * kv.y + qv.z * kv.z + qv.w * kv.w;
            }
        }

        // mask + online softmax
        const bool diag = (jb == ib);
        float mloc = -1e30f;
#pragma unroll
        for (int jj = 0; jj < 16; jj++) {
            s[jj] *= 0.125f;   // 1/sqrt(64)
            int jg = jb * 64 + q + jj * 4;
            if (diag && jg > tglob) s[jj] = -1e30f;
            mloc = fmaxf(mloc, s[jj]);
        }
        mloc = fmaxf(mloc, __shfl_xor_sync(0xffffffffu, mloc, 1));
        mloc = fmaxf(mloc, __shfl_xor_sync(0xffffffffu, mloc, 2));
        float mnew = fmaxf(m, mloc);

        float lloc = 0.f;
        float* Pr = Ps + r * ROWSTR;
#pragma unroll
        for (int jj = 0; jj < 16; jj++) {
            float p = __expf(s[jj] - mnew);    // -1e30 -> underflow -> 0
            Pr[q + jj * 4] = p;
            lloc += p;
        }
        lloc += __shfl_xor_sync(0xffffffffu, lloc, 1);
        lloc += __shfl_xor_sync(0xffffffffu, lloc, 2);

        float corr = __expf(m - mnew);
        m = mnew;
        l = l * corr + lloc;
#pragma unroll
        for (int u = 0; u < 4; u++) {
            o[u].x *= corr; o[u].y *= corr; o[u].z *= corr; o[u].w *= corr;
        }

        __syncwarp();   // Ps row r written by this warp's 4-lane group

        // O += P V   (thread owns d4 columns q + 4*u)
        const float4* V4s = reinterpret_cast<const float4*>(Vs);
        const float* PrR = Ps + r * ROWSTR;
#pragma unroll 8
        for (int j = 0; j < 64; j++) {
            float pv = PrR[j];
#pragma unroll
            for (int u = 0; u < 4; u++) {
                float4 vv = V4s[j * ROWSTR4 + q + u * 4];
                o[u].x += pv * vv.x;
                o[u].y += pv * vv.y;
                o[u].z += pv * vv.z;
                o[u].w += pv * vv.w;
            }
        }
    }

    // normalize + write out: g_attn[n][h*64 + d]
    float inv = 1.f / l;
    int n = b * T_ + tglob;
    float4* out4 = reinterpret_cast<float4*>(g_attn) + (size_t)n * (CMODEL >> 2) + hoff4;
#pragma unroll
    for (int u = 0; u < 4; u++) {
        float4 v = o[u];
        v.x *= inv; v.y *= inv; v.z *= inv; v.w *= inv;
        out4[q + u * 4] = v;
    }
}

// ---------------------------------------------------------------------------
// Launch
// ---------------------------------------------------------------------------
extern "C" void kernel_launch(void* const* d_in, const int* in_sizes, int n_in,
                              void* d_out, int out_size)
{
    const float* x     = (const float*)d_in[0];  // [2,2048,1024]
    const float* Wqkv  = (const float*)d_in[1];  // [3072,1024]
    const float* Wout  = (const float*)d_in[2];  // [1024,1024]
    float* out = (float*)d_out;                  // [2,2048,1024]

    float* qkv_ptr = nullptr;
    float* attn_ptr = nullptr;
    cudaGetSymbolAddress((void**)&qkv_ptr, g_qkv);
    cudaGetSymbolAddress((void**)&attn_ptr, g_attn);

    cudaFuncSetAttribute(attn_causal_kernel,
                         cudaFuncAttributeMaxDynamicSharedMemorySize, SMEM_ATTN);

    // 1) qkv = x @ Wqkv^T
    sgemm_nt<<<dim3(F3 / BN, NTOK / BM), 256>>>(x, Wqkv, qkv_ptr, NTOK, F3, CMODEL);

    // 2) causal flash attention
    attn_causal_kernel<<<dim3(T_ / 64, NHEADS, B_), 256, SMEM_ATTN>>>();

    // 3) out = attn @ Wout^T
    sgemm_nt<<<dim3(CMODEL / BN, NTOK / BM), 256>>>(attn_ptr, Wout, out, NTOK, CMODEL, CMODEL);
}

// round 3
// speedup vs baseline: 1.4330x; 1.4330x over previous
#include <cuda_runtime.h>
#include <cuda_bf16.h>
#include <cstdint>
#include <math.h>

// Problem constants
#define B_     2
#define T_     2048
#define CMODEL 1024
#define NHEADS 16
#define DHEAD  64
#define NTOK   (B_ * T_)          // 4096
#define F3     (3 * CMODEL)       // 3072

// Scratch (static device arrays — no runtime allocation)
__device__ __align__(256) float g_qkv[NTOK * F3];        // [n][3072]
__device__ __align__(256) float g_attn[NTOK * CMODEL];   // [n][1024]

// ---------------------------------------------------------------------------
// Helpers
// ---------------------------------------------------------------------------
__device__ __forceinline__ uint32_t smem_u32(const void* p) {
    uint32_t a;
    asm("{ .reg .u64 t; cvta.to.shared.u64 t, %1; cvt.u32.u64 %0, t; }"
        : "=r"(a) : "l"(p));
    return a;
}
__device__ __forceinline__ void cp16(uint32_t dst, const void* src) {
    asm volatile("cp.async.cg.shared.global [%0], [%1], 16;" :: "r"(dst), "l"(src));
}
#define CP_COMMIT() asm volatile("cp.async.commit_group;" ::: "memory")

__device__ __forceinline__ uint32_t f2tf(float x) {
    uint32_t r;
    asm("cvt.rna.tf32.f32 %0, %1;" : "=r"(r) : "f"(x));
    return r;
}
__device__ __forceinline__ void mma_tf32(float* c, const uint32_t* a, const uint32_t* b) {
    asm volatile(
        "mma.sync.aligned.m16n8k8.row.col.f32.tf32.tf32.f32 "
        "{%0,%1,%2,%3}, {%4,%5,%6,%7}, {%8,%9}, {%0,%1,%2,%3};"
        : "+f"(c[0]), "+f"(c[1]), "+f"(c[2]), "+f"(c[3])
        : "r"(a[0]), "r"(a[1]), "r"(a[2]), "r"(a[3]), "r"(b[0]), "r"(b[1]));
}

// ---------------------------------------------------------------------------
// mma.sync tf32 GEMM:  C[M,N] = A[M,K] * B[N,K]^T   (fp32 row-major, K contig)
// CTA 128x256, BK=32, 8 warps (warp tile 64x64), 3-stage cp.async pipeline.
// ---------------------------------------------------------------------------
#define BM 128
#define BN 256
#define BK 32
#define ASTR 36                         // smem row stride (floats): conflict-free
#define A_TILE_FL (BM * ASTR)           // 4608 floats
#define B_TILE_FL (BN * ASTR)           // 9216 floats
#define STAGE_FL  (A_TILE_FL + B_TILE_FL)
#define NSTAGE 3
#define GSMEM (NSTAGE * STAGE_FL * 4)   // 165888 bytes

__global__ __launch_bounds__(256) void gemm_mma_tf32(
    const float* __restrict__ A, const float* __restrict__ Bw,
    float* __restrict__ C, int M, int N, int K)
{
    extern __shared__ float sm[];
    const int tid = threadIdx.x;
    const int wid = tid >> 5, lane = tid & 31;
    const int g = lane >> 2, tg = lane & 3;
    const int m0 = blockIdx.y * BM, n0 = blockIdx.x * BN;
    const int wm = (wid & 1) * 64, wn = (wid >> 1) * 64;

    float acc[4][8][4];
#pragma unroll
    for (int mi = 0; mi < 4; mi++)
#pragma unroll
        for (int ni = 0; ni < 8; ni++)
#pragma unroll
            for (int j = 0; j < 4; j++) acc[mi][ni][j] = 0.f;

    const int KT = K / BK;

    auto load_stage = [&](int kt) {
        float* base = sm + (kt % NSTAGE) * STAGE_FL;
        const float* Ag = A + (size_t)m0 * K + kt * BK;
        const float* Bg = Bw + (size_t)n0 * K + kt * BK;
#pragma unroll
        for (int i = 0; i < 4; i++) {            // A: 1024 chunks of 16B
            int c = tid + i * 256;
            int row = c >> 3, col = c & 7;
            cp16(smem_u32(base + row * ASTR + col * 4),
                 Ag + (size_t)row * K + col * 4);
        }
        float* bb = base + A_TILE_FL;
#pragma unroll
        for (int i = 0; i < 8; i++) {            // B: 2048 chunks
            int c = tid + i * 256;
            int row = c >> 3, col = c & 7;
            cp16(smem_u32(bb + row * ASTR + col * 4),
                 Bg + (size_t)row * K + col * 4);
        }
    };

    load_stage(0); CP_COMMIT();
    load_stage(1); CP_COMMIT();

    for (int kt = 0; kt < KT; kt++) {
        if (kt + 2 < KT) load_stage(kt + 2);
        CP_COMMIT();
        asm volatile("cp.async.wait_group 2;" ::: "memory");
        __syncthreads();

        const float* base = sm + (kt % NSTAGE) * STAGE_FL;
        const float* As = base;
        const float* Bs = base + A_TILE_FL;
#pragma unroll
        for (int k8 = 0; k8 < 4; k8++) {
            const int k0 = k8 * 8;
            uint32_t af[4][4], bf[8][2];
#pragma unroll
            for (int mi = 0; mi < 4; mi++) {
                int r0 = wm + mi * 16 + g;
                af[mi][0] = f2tf(As[r0 * ASTR + k0 + tg]);
                af[mi][1] = f2tf(As[(r0 + 8) * ASTR + k0 + tg]);
                af[mi][2] = f2tf(As[r0 * ASTR + k0 + tg + 4]);
                af[mi][3] = f2tf(As[(r0 + 8) * ASTR + k0 + tg + 4]);
            }
#pragma unroll
            for (int ni = 0; ni < 8; ni++) {
                int rn = wn + ni * 8 + g;
                bf[ni][0] = f2tf(Bs[rn * ASTR + k0 + tg]);
                bf[ni][1] = f2tf(Bs[rn * ASTR + k0 + tg + 4]);
            }
#pragma unroll
            for (int mi = 0; mi < 4; mi++)
#pragma unroll
                for (int ni = 0; ni < 8; ni++)
                    mma_tf32(acc[mi][ni], af[mi], bf[ni]);
        }
        __syncthreads();
    }

    // Epilogue
#pragma unroll
    for (int mi = 0; mi < 4; mi++) {
        int r0 = m0 + wm + mi * 16 + g;
#pragma unroll
        for (int ni = 0; ni < 8; ni++) {
            int cc = n0 + wn + ni * 8 + 2 * tg;
            float2 v0 = make_float2(acc[mi][ni][0], acc[mi][ni][1]);
            float2 v1 = make_float2(acc[mi][ni][2], acc[mi][ni][3]);
            *reinterpret_cast<float2*>(&C[(size_t)r0 * N + cc]) = v0;
            *reinterpret_cast<float2*>(&C[(size_t)(r0 + 8) * N + cc]) = v1;
        }
    }
}

// ---------------------------------------------------------------------------
// Flash attention (causal), fp32 — unchanged (tensorize next round).
// ---------------------------------------------------------------------------
#define ROWSTR 68
#define ROWSTR4 17
#define TILE_F4 (64 * 16)
#define SMEM_ATTN (4 * 64 * ROWSTR * 4)

__global__ __launch_bounds__(256) void attn_causal_kernel()
{
    extern __shared__ float smf[];
    float* Qs = smf;
    float* Ks = smf + 64 * ROWSTR;
    float* Vs = smf + 2 * 64 * ROWSTR;
    float* Ps = smf + 3 * 64 * ROWSTR;

    const int ib = blockIdx.x;
    const int h  = blockIdx.y;
    const int b  = blockIdx.z;
    const int tid = threadIdx.x;
    const int r = tid >> 2;
    const int q = tid & 3;

    const float4* qkv4 = reinterpret_cast<const float4*>(g_qkv);
    const int rowstride4 = F3 >> 2;
    const int hoff4 = h * (DHEAD >> 2);

    {
        const int rb = b * T_ + ib * 64;
        for (int i = tid; i < TILE_F4; i += 256) {
            int row = i >> 4, c4 = i & 15;
            reinterpret_cast<float4*>(Qs)[row * ROWSTR4 + c4] =
                qkv4[(size_t)(rb + row) * rowstride4 + hoff4 + c4];
        }
    }

    float m = -1e30f, l = 0.f;
    float4 o[4];
#pragma unroll
    for (int u = 0; u < 4; u++) o[u] = make_float4(0.f, 0.f, 0.f, 0.f);

    const int tglob = ib * 64 + r;

    for (int jb = 0; jb <= ib; jb++) {
        __syncthreads();
        {
            const int kb = b * T_ + jb * 64;
            for (int i = tid; i < TILE_F4; i += 256) {
                int row = i >> 4, c4 = i & 15;
                size_t base = (size_t)(kb + row) * rowstride4;
                reinterpret_cast<float4*>(Ks)[row * ROWSTR4 + c4] =
                    qkv4[base + 256 + hoff4 + c4];
                reinterpret_cast<float4*>(Vs)[row * ROWSTR4 + c4] =
                    qkv4[base + 512 + hoff4 + c4];
            }
        }
        __syncthreads();

        float s[16];
#pragma unroll
        for (int jj = 0; jj < 16; jj++) s[jj] = 0.f;
        const float4* Qr = reinterpret_cast<const float4*>(Qs) + r * ROWSTR4;
        const float4* K4s = reinterpret_cast<const float4*>(Ks);
#pragma unroll
        for (int d4 = 0; d4 < 16; d4++) {
            float4 qv = Qr[d4];
#pragma unroll
            for (int jj = 0; jj < 16; jj++) {
                float4 kv = K4s[(q + jj * 4) * ROWSTR4 + d4];
                s[jj] += qv.x * kv.x + qv.y * kv.y + qv.z * kv.z + qv.w * kv.w;
            }
        }

        const bool diag = (jb == ib);
        float mloc = -1e30f;
#pragma unroll
        for (int jj = 0; jj < 16; jj++) {
            s[jj] *= 0.125f;
            int jg = jb * 64 + q + jj * 4;
            if (diag && jg > tglob) s[jj] = -1e30f;
            mloc = fmaxf(mloc, s[jj]);
        }
        mloc = fmaxf(mloc, __shfl_xor_sync(0xffffffffu, mloc, 1));
        mloc = fmaxf(mloc, __shfl_xor_sync(0xffffffffu, mloc, 2));
        float mnew = fmaxf(m, mloc);

        float lloc = 0.f;
        float* Pr = Ps + r * ROWSTR;
#pragma unroll
        for (int jj = 0; jj < 16; jj++) {
            float p = __expf(s[jj] - mnew);
            Pr[q + jj * 4] = p;
            lloc += p;
        }
        lloc += __shfl_xor_sync(0xffffffffu, lloc, 1);
        lloc += __shfl_xor_sync(0xffffffffu, lloc, 2);

        float corr = __expf(m - mnew);
        m = mnew;
        l = l * corr + lloc;
#pragma unroll
        for (int u = 0; u < 4; u++) {
            o[u].x *= corr; o[u].y *= corr; o[u].z *= corr; o[u].w *= corr;
        }

        __syncwarp();

        const float4* V4s = reinterpret_cast<const float4*>(Vs);
        const float* PrR = Ps + r * ROWSTR;
#pragma unroll 8
        for (int j = 0; j < 64; j++) {
            float pv = PrR[j];
#pragma unroll
            for (int u = 0; u < 4; u++) {
                float4 vv = V4s[j * ROWSTR4 + q + u * 4];
                o[u].x += pv * vv.x;
                o[u].y += pv * vv.y;
                o[u].z += pv * vv.z;
                o[u].w += pv * vv.w;
            }
        }
    }

    float inv = 1.f / l;
    int n = b * T_ + tglob;
    float4* out4 = reinterpret_cast<float4*>(g_attn) + (size_t)n * (CMODEL >> 2) + hoff4;
#pragma unroll
    for (int u = 0; u < 4; u++) {
        float4 v = o[u];
        v.x *= inv; v.y *= inv; v.z *= inv; v.w *= inv;
        out4[q + u * 4] = v;
    }
}

// ---------------------------------------------------------------------------
// Launch
// ---------------------------------------------------------------------------
extern "C" void kernel_launch(void* const* d_in, const int* in_sizes, int n_in,
                              void* d_out, int out_size)
{
    const float* x    = (const float*)d_in[0];
    const float* Wqkv = (const float*)d_in[1];
    const float* Wout = (const float*)d_in[2];
    float* out = (float*)d_out;

    float* qkv_ptr = nullptr;
    float* attn_ptr = nullptr;
    cudaGetSymbolAddress((void**)&qkv_ptr, g_qkv);
    cudaGetSymbolAddress((void**)&attn_ptr, g_attn);

    cudaFuncSetAttribute(gemm_mma_tf32,
                         cudaFuncAttributeMaxDynamicSharedMemorySize, GSMEM);
    cudaFuncSetAttribute(attn_causal_kernel,
                         cudaFuncAttributeMaxDynamicSharedMemorySize, SMEM_ATTN);

    // 1) qkv = x @ Wqkv^T
    gemm_mma_tf32<<<dim3(F3 / BN, NTOK / BM), 256, GSMEM>>>(x, Wqkv, qkv_ptr, NTOK, F3, CMODEL);

    // 2) causal flash attention
    attn_causal_kernel<<<dim3(T_ / 64, NHEADS, B_), 256, SMEM_ATTN>>>();

    // 3) out = attn @ Wout^T
    gemm_mma_tf32<<<dim3(CMODEL / BN, NTOK / BM), 256, GSMEM>>>(attn_ptr, Wout, out, NTOK, CMODEL, CMODEL);
}

// round 5
// speedup vs baseline: 4.5248x; 3.1575x over previous
#include <cuda_runtime.h>
#include <cuda_bf16.h>
#include <cstdint>
#include <math.h>

// Problem constants
#define B_     2
#define T_     2048
#define CMODEL 1024
#define NHEADS 16
#define DHEAD  64
#define NTOK   (B_ * T_)          // 4096
#define F3     (3 * CMODEL)       // 3072

// Scratch
__device__ __align__(256) float g_qkv[NTOK * F3];        // [n][3072], tf32-rounded
__device__ __align__(256) float g_attn[NTOK * CMODEL];   // [n][1024]

// ---------------------------------------------------------------------------
// Helpers
// ---------------------------------------------------------------------------
__device__ __forceinline__ uint32_t smem_u32(const void* p) {
    uint32_t a;
    asm("{ .reg .u64 t; cvta.to.shared.u64 t, %1; cvt.u32.u64 %0, t; }"
        : "=r"(a) : "l"(p));
    return a;
}
__device__ __forceinline__ void cp16(uint32_t dst, const void* src) {
    asm volatile("cp.async.cg.shared.global [%0], [%1], 16;" :: "r"(dst), "l"(src));
}
#define CP_COMMIT() asm volatile("cp.async.commit_group;" ::: "memory")

__device__ __forceinline__ uint32_t f2tf(float x) {
    uint32_t r;
    asm("cvt.rna.tf32.f32 %0, %1;" : "=r"(r) : "f"(x));
    return r;
}
__device__ __forceinline__ void mma_tf32(float* c, const uint32_t* a, const uint32_t* b) {
    asm volatile(
        "mma.sync.aligned.m16n8k8.row.col.f32.tf32.tf32.f32 "
        "{%0,%1,%2,%3}, {%4,%5,%6,%7}, {%8,%9}, {%0,%1,%2,%3};"
        : "+f"(c[0]), "+f"(c[1]), "+f"(c[2]), "+f"(c[3])
        : "r"(a[0]), "r"(a[1]), "r"(a[2]), "r"(a[3]), "r"(b[0]), "r"(b[1]));
}

// ---------------------------------------------------------------------------
// mma.sync tf32 GEMM:  C[M,N] = A[M,K] * B[N,K]^T
// CTA 128x256, BK=32, 8 warps (warp tile 64x64), 3-stage cp.async pipeline.
// If round_out != 0, output values are tf32-rounded (bitwise) before store.
// ---------------------------------------------------------------------------
#define BM 128
#define BN 256
#define BK 32
#define ASTR 36
#define A_TILE_FL (BM * ASTR)
#define B_TILE_FL (BN * ASTR)
#define STAGE_FL  (A_TILE_FL + B_TILE_FL)
#define NSTAGE 3
#define GSMEM (NSTAGE * STAGE_FL * 4)   // 165888 bytes

__global__ __launch_bounds__(256) void gemm_mma_tf32(
    const float* __restrict__ A, const float* __restrict__ Bw,
    float* __restrict__ C, int M, int N, int K, int round_out)
{
    extern __shared__ float sm[];
    const int tid = threadIdx.x;
    const int wid = tid >> 5, lane = tid & 31;
    const int g = lane >> 2, tg = lane & 3;
    const int m0 = blockIdx.y * BM, n0 = blockIdx.x * BN;
    const int wm = (wid & 1) * 64, wn = (wid >> 1) * 64;

    float acc[4][8][4];
#pragma unroll
    for (int mi = 0; mi < 4; mi++)
#pragma unroll
        for (int ni = 0; ni < 8; ni++)
#pragma unroll
            for (int j = 0; j < 4; j++) acc[mi][ni][j] = 0.f;

    const int KT = K / BK;

    auto load_stage = [&](int kt) {
        float* base = sm + (kt % NSTAGE) * STAGE_FL;
        const float* Ag = A + (size_t)m0 * K + kt * BK;
        const float* Bg = Bw + (size_t)n0 * K + kt * BK;
#pragma unroll
        for (int i = 0; i < 4; i++) {
            int c = tid + i * 256;
            int row = c >> 3, col = c & 7;
            cp16(smem_u32(base + row * ASTR + col * 4),
                 Ag + (size_t)row * K + col * 4);
        }
        float* bb = base + A_TILE_FL;
#pragma unroll
        for (int i = 0; i < 8; i++) {
            int c = tid + i * 256;
            int row = c >> 3, col = c & 7;
            cp16(smem_u32(bb + row * ASTR + col * 4),
                 Bg + (size_t)row * K + col * 4);
        }
    };

    load_stage(0); CP_COMMIT();
    load_stage(1); CP_COMMIT();

    for (int kt = 0; kt < KT; kt++) {
        if (kt + 2 < KT) load_stage(kt + 2);
        CP_COMMIT();
        asm volatile("cp.async.wait_group 2;" ::: "memory");
        __syncthreads();

        const float* base = sm + (kt % NSTAGE) * STAGE_FL;
        const float* As = base;
        const float* Bs = base + A_TILE_FL;
#pragma unroll
        for (int k8 = 0; k8 < 4; k8++) {
            const int k0 = k8 * 8;
            uint32_t af[4][4], bf[8][2];
#pragma unroll
            for (int mi = 0; mi < 4; mi++) {
                int r0 = wm + mi * 16 + g;
                af[mi][0] = f2tf(As[r0 * ASTR + k0 + tg]);
                af[mi][1] = f2tf(As[(r0 + 8) * ASTR + k0 + tg]);
                af[mi][2] = f2tf(As[r0 * ASTR + k0 + tg + 4]);
                af[mi][3] = f2tf(As[(r0 + 8) * ASTR + k0 + tg + 4]);
            }
#pragma unroll
            for (int ni = 0; ni < 8; ni++) {
                int rn = wn + ni * 8 + g;
                bf[ni][0] = f2tf(Bs[rn * ASTR + k0 + tg]);
                bf[ni][1] = f2tf(Bs[rn * ASTR + k0 + tg + 4]);
            }
#pragma unroll
            for (int mi = 0; mi < 4; mi++)
#pragma unroll
                for (int ni = 0; ni < 8; ni++)
                    mma_tf32(acc[mi][ni], af[mi], bf[ni]);
        }
        __syncthreads();
    }

#pragma unroll
    for (int mi = 0; mi < 4; mi++) {
        int r0 = m0 + wm + mi * 16 + g;
#pragma unroll
        for (int ni = 0; ni < 8; ni++) {
            int cc = n0 + wn + ni * 8 + 2 * tg;
            float v[4];
#pragma unroll
            for (int j = 0; j < 4; j++) {
                v[j] = round_out ? __uint_as_float(f2tf(acc[mi][ni][j]))
                                 : acc[mi][ni][j];
            }
            *reinterpret_cast<float2*>(&C[(size_t)r0 * N + cc]) = make_float2(v[0], v[1]);
            *reinterpret_cast<float2*>(&C[(size_t)(r0 + 8) * N + cc]) = make_float2(v[2], v[3]);
        }
    }
}

// ---------------------------------------------------------------------------
// Tensor-core flash attention (causal, tf32 mma.sync).
// CTA: 128 query rows of one (b,h). 8 warps x 16 rows.
// Key tiles of 64, double-buffered cp.async. Q frags register-resident.
// g_qkv values are already tf32-rounded (GEMM1 epilogue) -> raw bits to mma.
// ---------------------------------------------------------------------------
#define BR 128
#define BC 64
#define QSTR 68
#define KSTR 68
#define VSTR 72
#define PSTR 68

#define OFF_Q 0
#define OFF_K (BR * QSTR)                     // 8704
#define OFF_V (OFF_K + 2 * BC * KSTR)         // 17408
#define OFF_P (OFF_V + 2 * BC * VSTR)         // 26624
#define ATTN_SMEM_FL (OFF_P + 8 * 16 * PSTR)  // 35328
#define ATTN_SMEM (ATTN_SMEM_FL * 4)          // 141312 bytes

__global__ __launch_bounds__(256) void attn_mma_kernel()
{
    extern __shared__ float sm[];
    const int tid = threadIdx.x;
    const int wid = tid >> 5, lane = tid & 31;
    const int g = lane >> 2, tg = lane & 3;
    const int ib = (int)gridDim.x - 1 - (int)blockIdx.x;   // big tiles first
    const int h = blockIdx.y, b = blockIdx.z;
    const int ibase = ib * BR;
    const int hoff = h * DHEAD;
    const int wm = wid * 16;

    // ---- async load Q tile + KV tile 0 (group 0) ----
    {
        const float* Qg = g_qkv + (size_t)(b * T_ + ibase) * F3 + hoff;
        for (int i = tid; i < BR * 16; i += 256) {
            int row = i >> 4, c4 = i & 15;
            cp16(smem_u32(sm + OFF_Q + row * QSTR + c4 * 4),
                 Qg + (size_t)row * F3 + c4 * 4);
        }
    }
    auto load_kv = [&](int jb) {
        int buf = jb & 1;
        const float* Kg = g_qkv + (size_t)(b * T_ + jb * BC) * F3 + CMODEL + hoff;
        const float* Vg = Kg + CMODEL;
        float* Kb = sm + OFF_K + buf * BC * KSTR;
        float* Vb = sm + OFF_V + buf * BC * VSTR;
        for (int i = tid; i < BC * 16; i += 256) {
            int row = i >> 4, c4 = i & 15;
            cp16(smem_u32(Kb + row * KSTR + c4 * 4), Kg + (size_t)row * F3 + c4 * 4);
            cp16(smem_u32(Vb + row * VSTR + c4 * 4), Vg + (size_t)row * F3 + c4 * 4);
        }
    };
    load_kv(0);
    CP_COMMIT();   // group 0: Q + KV0

    const int NT = 2 * ib + 2;

    float m0 = -1e30f, m1 = -1e30f, l0 = 0.f, l1 = 0.f;
    float o[8][4];
#pragma unroll
    for (int ni = 0; ni < 8; ni++)
#pragma unroll
        for (int j = 0; j < 4; j++) o[ni][j] = 0.f;

    uint32_t qf[8][4];
    float* Pw = sm + OFF_P + wid * 16 * PSTR;

    for (int jb = 0; jb < NT; jb++) {
        if (jb + 1 < NT) {
            load_kv(jb + 1);
            CP_COMMIT();
            asm volatile("cp.async.wait_group 1;" ::: "memory");
        } else {
            asm volatile("cp.async.wait_group 0;" ::: "memory");
        }
        __syncthreads();

        if (jb == 0) {
            // Q fragments: register-resident for the whole CTA lifetime
            const float* Qs = sm + OFF_Q;
#pragma unroll
            for (int k8 = 0; k8 < 8; k8++) {
                qf[k8][0] = __float_as_uint(Qs[(wm + g) * QSTR + k8 * 8 + tg]);
                qf[k8][1] = __float_as_uint(Qs[(wm + g + 8) * QSTR + k8 * 8 + tg]);
                qf[k8][2] = __float_as_uint(Qs[(wm + g) * QSTR + k8 * 8 + tg + 4]);
                qf[k8][3] = __float_as_uint(Qs[(wm + g + 8) * QSTR + k8 * 8 + tg + 4]);
            }
        }

        const int jbase = jb * BC;
        const bool skip = (jbase > ibase + wm + 15);   // tile fully masked for warp
        if (!skip) {
            const float* Kb = sm + OFF_K + (jb & 1) * BC * KSTR;
            const float* Vb = sm + OFF_V + (jb & 1) * BC * VSTR;

            // ---- S = Q K^T ----
            float s[8][4];
#pragma unroll
            for (int ni = 0; ni < 8; ni++)
#pragma unroll
                for (int j = 0; j < 4; j++) s[ni][j] = 0.f;
#pragma unroll
            for (int k8 = 0; k8 < 8; k8++) {
                const int k0 = k8 * 8;
#pragma unroll
                for (int ni = 0; ni < 8; ni++) {
                    uint32_t bf[2];
                    bf[0] = __float_as_uint(Kb[(ni * 8 + g) * KSTR + k0 + tg]);
                    bf[1] = __float_as_uint(Kb[(ni * 8 + g) * KSTR + k0 + tg + 4]);
                    mma_tf32(s[ni], qf[k8], bf);
                }
            }

            // ---- scale + causal mask ----
            const int qr0 = ibase + wm + g;
            const int qr1 = qr0 + 8;
            const bool full = (jbase + BC - 1 <= ibase + wm);
#pragma unroll
            for (int ni = 0; ni < 8; ni++) {
                s[ni][0] *= 0.125f; s[ni][1] *= 0.125f;
                s[ni][2] *= 0.125f; s[ni][3] *= 0.125f;
                if (!full) {
                    int kc = jbase + ni * 8 + 2 * tg;
                    if (kc > qr0)     s[ni][0] = -1e30f;
                    if (kc + 1 > qr0) s[ni][1] = -1e30f;
                    if (kc > qr1)     s[ni][2] = -1e30f;
                    if (kc + 1 > qr1) s[ni][3] = -1e30f;
                }
            }

            // ---- online softmax ----
            float rm0 = -1e30f, rm1 = -1e30f;
#pragma unroll
            for (int ni = 0; ni < 8; ni++) {
                rm0 = fmaxf(rm0, fmaxf(s[ni][0], s[ni][1]));
                rm1 = fmaxf(rm1, fmaxf(s[ni][2], s[ni][3]));
            }
            rm0 = fmaxf(rm0, __shfl_xor_sync(0xffffffffu, rm0, 1));
            rm0 = fmaxf(rm0, __shfl_xor_sync(0xffffffffu, rm0, 2));
            rm1 = fmaxf(rm1, __shfl_xor_sync(0xffffffffu, rm1, 1));
            rm1 = fmaxf(rm1, __shfl_xor_sync(0xffffffffu, rm1, 2));
            float mn0 = fmaxf(m0, rm0), mn1 = fmaxf(m1, rm1);
            float c0 = __expf(m0 - mn0), c1 = __expf(m1 - mn1);
            m0 = mn0; m1 = mn1;

            float ls0 = 0.f, ls1 = 0.f;
#pragma unroll
            for (int ni = 0; ni < 8; ni++) {
                float p0 = __expf(s[ni][0] - mn0);
                float p1 = __expf(s[ni][1] - mn0);
                float p2 = __expf(s[ni][2] - mn1);
                float p3 = __expf(s[ni][3] - mn1);
                ls0 += p0 + p1; ls1 += p2 + p3;
                *reinterpret_cast<float2*>(&Pw[g * PSTR + ni * 8 + 2 * tg]) =
                    make_float2(p0, p1);
                *reinterpret_cast<float2*>(&Pw[(g + 8) * PSTR + ni * 8 + 2 * tg]) =
                    make_float2(p2, p3);
            }
            ls0 += __shfl_xor_sync(0xffffffffu, ls0, 1);
            ls0 += __shfl_xor_sync(0xffffffffu, ls0, 2);
            ls1 += __shfl_xor_sync(0xffffffffu, ls1, 1);
            ls1 += __shfl_xor_sync(0xffffffffu, ls1, 2);
            l0 = l0 * c0 + ls0;
            l1 = l1 * c1 + ls1;
#pragma unroll
            for (int ni = 0; ni < 8; ni++) {
                o[ni][0] *= c0; o[ni][1] *= c0;
                o[ni][2] *= c1; o[ni][3] *= c1;
            }
            __syncwarp();

            // ---- O += P V ----
#pragma unroll
            for (int k8 = 0; k8 < 8; k8++) {
                const int k0 = k8 * 8;
                uint32_t ap[4];
                ap[0] = f2tf(Pw[g * PSTR + k0 + tg]);
                ap[1] = f2tf(Pw[(g + 8) * PSTR + k0 + tg]);
                ap[2] = f2tf(Pw[g * PSTR + k0 + tg + 4]);
                ap[3] = f2tf(Pw[(g + 8) * PSTR + k0 + tg + 4]);
#pragma unroll
                for (int ni = 0; ni < 8; ni++) {
                    uint32_t bf[2];
                    bf[0] = __float_as_uint(Vb[(k0 + tg) * VSTR + ni * 8 + g]);
                    bf[1] = __float_as_uint(Vb[(k0 + tg + 4) * VSTR + ni * 8 + g]);
                    mma_tf32(o[ni], ap, bf);
                }
            }
            __syncwarp();   // Pw reuse next tile
        }
        __syncthreads();   // buffer consumed before prefetch overwrites
    }

    // ---- epilogue: O / l -> g_attn[b*T+row][hoff + d] ----
    const float inv0 = 1.f / l0, inv1 = 1.f / l1;
    float* O0 = g_attn + (size_t)(b * T_ + ibase + wm + g) * CMODEL + hoff;
    float* O1 = O0 + 8 * CMODEL;
#pragma unroll
    for (int ni = 0; ni < 8; ni++) {
        int cc = ni * 8 + 2 * tg;
        *reinterpret_cast<float2*>(O0 + cc) = make_float2(o[ni][0] * inv0, o[ni][1] * inv0);
        *reinterpret_cast<float2*>(O1 + cc) = make_float2(o[ni][2] * inv1, o[ni][3] * inv1);
    }
}

// ---------------------------------------------------------------------------
// Launch
// ---------------------------------------------------------------------------
extern "C" void kernel_launch(void* const* d_in, const int* in_sizes, int n_in,
                              void* d_out, int out_size)
{
    const float* x    = (const float*)d_in[0];
    const float* Wqkv = (const float*)d_in[1];
    const float* Wout = (const float*)d_in[2];
    float* out = (float*)d_out;

    float* qkv_ptr = nullptr;
    float* attn_ptr = nullptr;
    cudaGetSymbolAddress((void**)&qkv_ptr, g_qkv);
    cudaGetSymbolAddress((void**)&attn_ptr, g_attn);

    cudaFuncSetAttribute(gemm_mma_tf32,
                         cudaFuncAttributeMaxDynamicSharedMemorySize, GSMEM);
    cudaFuncSetAttribute(attn_mma_kernel,
                         cudaFuncAttributeMaxDynamicSharedMemorySize, ATTN_SMEM);

    // 1) qkv = x @ Wqkv^T   (outputs tf32-rounded for the attention mma)
    gemm_mma_tf32<<<dim3(F3 / BN, NTOK / BM), 256, GSMEM>>>(
        x, Wqkv, qkv_ptr, NTOK, F3, CMODEL, 1);

    // 2) causal flash attention (tensor cores)
    attn_mma_kernel<<<dim3(T_ / BR, NHEADS, B_), 256, ATTN_SMEM>>>();

    // 3) out = attn @ Wout^T
    gemm_mma_tf32<<<dim3(CMODEL / BN, NTOK / BM), 256, GSMEM>>>(
        attn_ptr, Wout, out, NTOK, CMODEL, CMODEL, 0);
}

// round 6
// speedup vs baseline: 5.0460x; 1.1152x over previous
#include <cuda_runtime.h>
#include <cuda_bf16.h>
#include <cstdint>
#include <math.h>

// Problem constants
#define B_     2
#define T_     2048
#define CMODEL 1024
#define NHEADS 16
#define DHEAD  64
#define NTOK   (B_ * T_)          // 4096
#define F3     (3 * CMODEL)       // 3072

// Scratch (static device arrays)
__device__ __align__(256) float g_qkv[NTOK * F3];        // tf32-rounded, q pre-scaled
__device__ __align__(256) float g_attn[NTOK * CMODEL];   // tf32-rounded
__device__ __align__(256) float g_xr[NTOK * CMODEL];     // tf32-rounded x
__device__ __align__(256) float g_wqr[F3 * CMODEL];      // tf32-rounded W_qkv
__device__ __align__(256) float g_wor[CMODEL * CMODEL];  // tf32-rounded W_out

// ---------------------------------------------------------------------------
// Helpers
// ---------------------------------------------------------------------------
__device__ __forceinline__ uint32_t smem_u32(const void* p) {
    uint32_t a;
    asm("{ .reg .u64 t; cvta.to.shared.u64 t, %1; cvt.u32.u64 %0, t; }"
        : "=r"(a) : "l"(p));
    return a;
}
__device__ __forceinline__ void cp16(uint32_t dst, const void* src) {
    asm volatile("cp.async.cg.shared.global [%0], [%1], 16;" :: "r"(dst), "l"(src));
}
#define CP_COMMIT() asm volatile("cp.async.commit_group;" ::: "memory")
#define CP_WAIT0()  asm volatile("cp.async.wait_group 0;" ::: "memory")
#define CP_WAIT1()  asm volatile("cp.async.wait_group 1;" ::: "memory")

__device__ __forceinline__ uint32_t f2tf(float x) {
    uint32_t r;
    asm("cvt.rna.tf32.f32 %0, %1;" : "=r"(r) : "f"(x));
    return r;
}
__device__ __forceinline__ void mma_tf32(float* c, const uint32_t* a, const uint32_t* b) {
    asm volatile(
        "mma.sync.aligned.m16n8k8.row.col.f32.tf32.tf32.f32 "
        "{%0,%1,%2,%3}, {%4,%5,%6,%7}, {%8,%9}, {%0,%1,%2,%3};"
        : "+f"(c[0]), "+f"(c[1]), "+f"(c[2]), "+f"(c[3])
        : "r"(a[0]), "r"(a[1]), "r"(a[2]), "r"(a[3]), "r"(b[0]), "r"(b[1]));
}

// ---------------------------------------------------------------------------
// Pre-round pass: three fp32 arrays -> tf32-rounded copies (bitwise fp32)
// ---------------------------------------------------------------------------
__global__ __launch_bounds__(256) void round_tf32_kernel(
    const float4* __restrict__ a, float4* __restrict__ da, int na4,
    const float4* __restrict__ b, float4* __restrict__ db, int nb4,
    const float4* __restrict__ c, float4* __restrict__ dc, int nc4)
{
    int total = na4 + nb4 + nc4;
    for (int i = blockIdx.x * blockDim.x + threadIdx.x; i < total;
         i += gridDim.x * blockDim.x) {
        const float4* s; float4* d; int j;
        if (i < na4)            { s = a; d = da; j = i; }
        else if (i < na4 + nb4) { s = b; d = db; j = i - na4; }
        else                    { s = c; d = dc; j = i - na4 - nb4; }
        float4 v = s[j];
        v.x = __uint_as_float(f2tf(v.x));
        v.y = __uint_as_float(f2tf(v.y));
        v.z = __uint_as_float(f2tf(v.z));
        v.w = __uint_as_float(f2tf(v.w));
        d[j] = v;
    }
}

// ---------------------------------------------------------------------------
// mma.sync tf32 GEMM: C[M,N] = A[M,K] * B[N,K]^T. Inputs pre-rounded to tf32.
// CTA 128x256, BK=32, 8 warps, 3-stage cp.async, 1 syncthreads per k-tile,
// double-buffered fragment registers. round_out: tf32-round C, scale cols<1024
// by 0.125 (for Q).
// ---------------------------------------------------------------------------
#define BM 128
#define BN 256
#define BK 32
#define ASTR 36
#define A_TILE_FL (BM * ASTR)
#define B_TILE_FL (BN * ASTR)
#define STAGE_FL  (A_TILE_FL + B_TILE_FL)
#define NSTAGE 3
#define GSMEM (NSTAGE * STAGE_FL * 4)   // 165888 bytes

__global__ __launch_bounds__(256) void gemm_mma_tf32(
    const float* __restrict__ A, const float* __restrict__ Bw,
    float* __restrict__ C, int M, int N, int K, int round_out)
{
    extern __shared__ float sm[];
    const int tid = threadIdx.x;
    const int wid = tid >> 5, lane = tid & 31;
    const int g = lane >> 2, tg = lane & 3;
    const int m0 = blockIdx.y * BM, n0 = blockIdx.x * BN;
    const int wm = (wid & 1) * 64, wn = (wid >> 1) * 64;

    float acc[4][8][4];
#pragma unroll
    for (int mi = 0; mi < 4; mi++)
#pragma unroll
        for (int ni = 0; ni < 8; ni++)
#pragma unroll
            for (int j = 0; j < 4; j++) acc[mi][ni][j] = 0.f;

    const int KT = K / BK;

    auto load_stage = [&](int kt) {
        float* base = sm + (kt % NSTAGE) * STAGE_FL;
        const float* Ag = A + (size_t)m0 * K + kt * BK;
        const float* Bg = Bw + (size_t)n0 * K + kt * BK;
#pragma unroll
        for (int i = 0; i < 4; i++) {
            int c = tid + i * 256;
            int row = c >> 3, col = c & 7;
            cp16(smem_u32(base + row * ASTR + col * 4),
                 Ag + (size_t)row * K + col * 4);
        }
        float* bb = base + A_TILE_FL;
#pragma unroll
        for (int i = 0; i < 8; i++) {
            int c = tid + i * 256;
            int row = c >> 3, col = c & 7;
            cp16(smem_u32(bb + row * ASTR + col * 4),
                 Bg + (size_t)row * K + col * 4);
        }
    };

    load_stage(0); CP_COMMIT();
    load_stage(1); CP_COMMIT();

    for (int kt = 0; kt < KT; kt++) {
        CP_WAIT1();            // stage kt resident
        __syncthreads();       // all warps finished stage kt-1
        if (kt + 2 < KT) load_stage(kt + 2);
        CP_COMMIT();           // commit every iter to keep group counts aligned

        const float* As = sm + (kt % NSTAGE) * STAGE_FL;
        const float* Bs = As + A_TILE_FL;

        uint32_t af[2][4][4], bf[2][8][2];
        auto ldfrag = [&](int k8, uint32_t (*afb)[4], uint32_t (*bfb)[2]) {
            const int k0 = k8 * 8;
#pragma unroll
            for (int mi = 0; mi < 4; mi++) {
                int r0 = wm + mi * 16 + g;
                afb[mi][0] = __float_as_uint(As[r0 * ASTR + k0 + tg]);
                afb[mi][1] = __float_as_uint(As[(r0 + 8) * ASTR + k0 + tg]);
                afb[mi][2] = __float_as_uint(As[r0 * ASTR + k0 + tg + 4]);
                afb[mi][3] = __float_as_uint(As[(r0 + 8) * ASTR + k0 + tg + 4]);
            }
#pragma unroll
            for (int ni = 0; ni < 8; ni++) {
                int rn = wn + ni * 8 + g;
                bfb[ni][0] = __float_as_uint(Bs[rn * ASTR + k0 + tg]);
                bfb[ni][1] = __float_as_uint(Bs[rn * ASTR + k0 + tg + 4]);
            }
        };

        ldfrag(0, af[0], bf[0]);
#pragma unroll
        for (int k8 = 0; k8 < 4; k8++) {
            const int cur = k8 & 1, nxt = cur ^ 1;
            if (k8 < 3) ldfrag(k8 + 1, af[nxt], bf[nxt]);
#pragma unroll
            for (int mi = 0; mi < 4; mi++)
#pragma unroll
                for (int ni = 0; ni < 8; ni++)
                    mma_tf32(acc[mi][ni], af[cur][mi], bf[cur][ni]);
        }
    }

#pragma unroll
    for (int mi = 0; mi < 4; mi++) {
        int r0 = m0 + wm + mi * 16 + g;
#pragma unroll
        for (int ni = 0; ni < 8; ni++) {
            int cc = n0 + wn + ni * 8 + 2 * tg;
            float v[4];
            float sc = 1.f;
            if (round_out && cc < CMODEL) sc = 0.125f;   // pre-scale Q by 1/sqrt(d)
#pragma unroll
            for (int j = 0; j < 4; j++) {
                v[j] = round_out ? __uint_as_float(f2tf(acc[mi][ni][j] * sc))
                                 : acc[mi][ni][j];
            }
            *reinterpret_cast<float2*>(&C[(size_t)r0 * N + cc]) = make_float2(v[0], v[1]);
            *reinterpret_cast<float2*>(&C[(size_t)(r0 + 8) * N + cc]) = make_float2(v[2], v[3]);
        }
    }
}

// ---------------------------------------------------------------------------
// Tensor-core flash attention (causal, tf32 mma.sync).
// CTA: 128 query rows of one (b,h). 8 warps x 16 rows. Q pre-scaled by 0.125.
// Key tiles of 64, double-buffered cp.async, 1 syncthreads per tile.
// All smem values are tf32-rounded bit patterns -> raw bits into mma.
// ---------------------------------------------------------------------------
#define BR 128
#define BC 64
#define QSTR 68
#define KSTR 68
#define VSTR 72
#define PSTR 68

#define OFF_Q 0
#define OFF_K (BR * QSTR)                     // 8704
#define OFF_V (OFF_K + 2 * BC * KSTR)         // 17408
#define OFF_P (OFF_V + 2 * BC * VSTR)         // 26624
#define ATTN_SMEM_FL (OFF_P + 8 * 16 * PSTR)  // 35328
#define ATTN_SMEM (ATTN_SMEM_FL * 4)          // 141312 bytes

__global__ __launch_bounds__(256) void attn_mma_kernel()
{
    extern __shared__ float sm[];
    const int tid = threadIdx.x;
    const int wid = tid >> 5, lane = tid & 31;
    const int g = lane >> 2, tg = lane & 3;
    const int ib = (int)gridDim.x - 1 - (int)blockIdx.x;   // big tiles first
    const int h = blockIdx.y, b = blockIdx.z;
    const int ibase = ib * BR;
    const int hoff = h * DHEAD;
    const int wm = wid * 16;

    // ---- async load Q tile + KV tile 0 ----
    {
        const float* Qg = g_qkv + (size_t)(b * T_ + ibase) * F3 + hoff;
        for (int i = tid; i < BR * 16; i += 256) {
            int row = i >> 4, c4 = i & 15;
            cp16(smem_u32(sm + OFF_Q + row * QSTR + c4 * 4),
                 Qg + (size_t)row * F3 + c4 * 4);
        }
    }
    auto load_kv = [&](int jb) {
        int buf = jb & 1;
        const float* Kg = g_qkv + (size_t)(b * T_ + jb * BC) * F3 + CMODEL + hoff;
        const float* Vg = Kg + CMODEL;
        float* Kb = sm + OFF_K + buf * BC * KSTR;
        float* Vb = sm + OFF_V + buf * BC * VSTR;
        for (int i = tid; i < BC * 16; i += 256) {
            int row = i >> 4, c4 = i & 15;
            cp16(smem_u32(Kb + row * KSTR + c4 * 4), Kg + (size_t)row * F3 + c4 * 4);
            cp16(smem_u32(Vb + row * VSTR + c4 * 4), Vg + (size_t)row * F3 + c4 * 4);
        }
    };
    load_kv(0);
    CP_COMMIT();

    const int NT = 2 * ib + 2;

    float m0 = -1e30f, m1 = -1e30f, l0 = 0.f, l1 = 0.f;
    float o[8][4];
#pragma unroll
    for (int ni = 0; ni < 8; ni++)
#pragma unroll
        for (int j = 0; j < 4; j++) o[ni][j] = 0.f;

    // Q fragments: register-resident for the whole CTA lifetime
    CP_WAIT0();
    __syncthreads();
    uint32_t qf[8][4];
    {
        const float* Qs = sm + OFF_Q;
#pragma unroll
        for (int k8 = 0; k8 < 8; k8++) {
            qf[k8][0] = __float_as_uint(Qs[(wm + g) * QSTR + k8 * 8 + tg]);
            qf[k8][1] = __float_as_uint(Qs[(wm + g + 8) * QSTR + k8 * 8 + tg]);
            qf[k8][2] = __float_as_uint(Qs[(wm + g) * QSTR + k8 * 8 + tg + 4]);
            qf[k8][3] = __float_as_uint(Qs[(wm + g + 8) * QSTR + k8 * 8 + tg + 4]);
        }
    }

    float* Pw = sm + OFF_P + wid * 16 * PSTR;

    for (int jb = 0; jb < NT; jb++) {
        if (jb > 0) {
            CP_WAIT0();        // KV jb resident
            __syncthreads();   // all warps done with buffer (jb-1)&1
        }
        if (jb + 1 < NT) {
            load_kv(jb + 1);   // writes buffer (jb+1)&1, safe: compute jb-1 done
            CP_COMMIT();
        }

        const int jbase = jb * BC;
        const bool skip = (jbase > ibase + wm + 15);   // tile fully masked for warp
        if (!skip) {
            const float* Kb = sm + OFF_K + (jb & 1) * BC * KSTR;
            const float* Vb = sm + OFF_V + (jb & 1) * BC * VSTR;

            // ---- S = Q K^T  (Q pre-scaled by 0.125) ----
            float s[8][4];
#pragma unroll
            for (int ni = 0; ni < 8; ni++)
#pragma unroll
                for (int j = 0; j < 4; j++) s[ni][j] = 0.f;
#pragma unroll
            for (int k8 = 0; k8 < 8; k8++) {
                const int k0 = k8 * 8;
#pragma unroll
                for (int ni = 0; ni < 8; ni++) {
                    uint32_t bf[2];
                    bf[0] = __float_as_uint(Kb[(ni * 8 + g) * KSTR + k0 + tg]);
                    bf[1] = __float_as_uint(Kb[(ni * 8 + g) * KSTR + k0 + tg + 4]);
                    mma_tf32(s[ni], qf[k8], bf);
                }
            }

            // ---- causal mask ----
            const int qr0 = ibase + wm + g;
            const int qr1 = qr0 + 8;
            const bool full = (jbase + BC - 1 <= ibase + wm);
            if (!full) {
#pragma unroll
                for (int ni = 0; ni < 8; ni++) {
                    int kc = jbase + ni * 8 + 2 * tg;
                    if (kc > qr0)     s[ni][0] = -1e30f;
                    if (kc + 1 > qr0) s[ni][1] = -1e30f;
                    if (kc > qr1)     s[ni][2] = -1e30f;
                    if (kc + 1 > qr1) s[ni][3] = -1e30f;
                }
            }

            // ---- online softmax ----
            float rm0 = -1e30f, rm1 = -1e30f;
#pragma unroll
            for (int ni = 0; ni < 8; ni++) {
                rm0 = fmaxf(rm0, fmaxf(s[ni][0], s[ni][1]));
                rm1 = fmaxf(rm1, fmaxf(s[ni][2], s[ni][3]));
            }
            rm0 = fmaxf(rm0, __shfl_xor_sync(0xffffffffu, rm0, 1));
            rm0 = fmaxf(rm0, __shfl_xor_sync(0xffffffffu, rm0, 2));
            rm1 = fmaxf(rm1, __shfl_xor_sync(0xffffffffu, rm1, 1));
            rm1 = fmaxf(rm1, __shfl_xor_sync(0xffffffffu, rm1, 2));
            float mn0 = fmaxf(m0, rm0), mn1 = fmaxf(m1, rm1);
            float c0 = __expf(m0 - mn0), c1 = __expf(m1 - mn1);
            m0 = mn0; m1 = mn1;

            float ls0 = 0.f, ls1 = 0.f;
#pragma unroll
            for (int ni = 0; ni < 8; ni++) {
                float p0 = __expf(s[ni][0] - mn0);
                float p1 = __expf(s[ni][1] - mn0);
                float p2 = __expf(s[ni][2] - mn1);
                float p3 = __expf(s[ni][3] - mn1);
                ls0 += p0 + p1; ls1 += p2 + p3;
                *reinterpret_cast<float2*>(&Pw[g * PSTR + ni * 8 + 2 * tg]) =
                    make_float2(__uint_as_float(f2tf(p0)), __uint_as_float(f2tf(p1)));
                *reinterpret_cast<float2*>(&Pw[(g + 8) * PSTR + ni * 8 + 2 * tg]) =
                    make_float2(__uint_as_float(f2tf(p2)), __uint_as_float(f2tf(p3)));
            }
            ls0 += __shfl_xor_sync(0xffffffffu, ls0, 1);
            ls0 += __shfl_xor_sync(0xffffffffu, ls0, 2);
            ls1 += __shfl_xor_sync(0xffffffffu, ls1, 1);
            ls1 += __shfl_xor_sync(0xffffffffu, ls1, 2);
            l0 = l0 * c0 + ls0;
            l1 = l1 * c1 + ls1;
#pragma unroll
            for (int ni = 0; ni < 8; ni++) {
                o[ni][0] *= c0; o[ni][1] *= c0;
                o[ni][2] *= c1; o[ni][3] *= c1;
            }
            __syncwarp();

            // ---- O += P V ----
#pragma unroll
            for (int k8 = 0; k8 < 8; k8++) {
                const int k0 = k8 * 8;
                uint32_t ap[4];
                ap[0] = __float_as_uint(Pw[g * PSTR + k0 + tg]);
                ap[1] = __float_as_uint(Pw[(g + 8) * PSTR + k0 + tg]);
                ap[2] = __float_as_uint(Pw[g * PSTR + k0 + tg + 4]);
                ap[3] = __float_as_uint(Pw[(g + 8) * PSTR + k0 + tg + 4]);
#pragma unroll
                for (int ni = 0; ni < 8; ni++) {
                    uint32_t bf[2];
                    bf[0] = __float_as_uint(Vb[(k0 + tg) * VSTR + ni * 8 + g]);
                    bf[1] = __float_as_uint(Vb[(k0 + tg + 4) * VSTR + ni * 8 + g]);
                    mma_tf32(o[ni], ap, bf);
                }
            }
            __syncwarp();   // Pw reuse next tile
        }
    }

    // ---- epilogue: O / l, tf32-rounded for GEMM3 ----
    const float inv0 = 1.f / l0, inv1 = 1.f / l1;
    float* O0 = g_attn + (size_t)(b * T_ + ibase + wm + g) * CMODEL + hoff;
    float* O1 = O0 + 8 * CMODEL;
#pragma unroll
    for (int ni = 0; ni < 8; ni++) {
        int cc = ni * 8 + 2 * tg;
        *reinterpret_cast<float2*>(O0 + cc) = make_float2(
            __uint_as_float(f2tf(o[ni][0] * inv0)),
            __uint_as_float(f2tf(o[ni][1] * inv0)));
        *reinterpret_cast<float2*>(O1 + cc) = make_float2(
            __uint_as_float(f2tf(o[ni][2] * inv1)),
            __uint_as_float(f2tf(o[ni][3] * inv1)));
    }
}

// ---------------------------------------------------------------------------
// Launch
// ---------------------------------------------------------------------------
extern "C" void kernel_launch(void* const* d_in, const int* in_sizes, int n_in,
                              void* d_out, int out_size)
{
    const float* x    = (const float*)d_in[0];
    const float* Wqkv = (const float*)d_in[1];
    const float* Wout = (const float*)d_in[2];
    float* out = (float*)d_out;

    float *qkv_ptr, *attn_ptr, *xr_ptr, *wqr_ptr, *wor_ptr;
    cudaGetSymbolAddress((void**)&qkv_ptr, g_qkv);
    cudaGetSymbolAddress((void**)&attn_ptr, g_attn);
    cudaGetSymbolAddress((void**)&xr_ptr, g_xr);
    cudaGetSymbolAddress((void**)&wqr_ptr, g_wqr);
    cudaGetSymbolAddress((void**)&wor_ptr, g_wor);

    cudaFuncSetAttribute(gemm_mma_tf32,
                         cudaFuncAttributeMaxDynamicSharedMemorySize, GSMEM);
    cudaFuncSetAttribute(attn_mma_kernel,
                         cudaFuncAttributeMaxDynamicSharedMemorySize, ATTN_SMEM);

    // 0) pre-round inputs to tf32 (removes all cvt from GEMM mainloops)
    round_tf32_kernel<<<1024, 256>>>(
        (const float4*)x,    (float4*)xr_ptr,  (NTOK * CMODEL) / 4,
        (const float4*)Wqkv, (float4*)wqr_ptr, (F3 * CMODEL) / 4,
        (const float4*)Wout, (float4*)wor_ptr, (CMODEL * CMODEL) / 4);

    // 1) qkv = x @ Wqkv^T  (round output; scale q columns by 0.125)
    gemm_mma_tf32<<<dim3(F3 / BN, NTOK / BM), 256, GSMEM>>>(
        xr_ptr, wqr_ptr, qkv_ptr, NTOK, F3, CMODEL, 1);

    // 2) causal flash attention (tensor cores)
    attn_mma_kernel<<<dim3(T_ / BR, NHEADS, B_), 256, ATTN_SMEM>>>();

    // 3) out = attn @ Wout^T
    gemm_mma_tf32<<<dim3(CMODEL / BN, NTOK / BM), 256, GSMEM>>>(
        attn_ptr, wor_ptr, out, NTOK, CMODEL, CMODEL, 0);
}